// round 3
// baseline (speedup 1.0000x reference)
#include <cuda_runtime.h>
#include <cuda_bf16.h>
#include <math.h>

// ---------------- problem constants ----------------
#define BATCH 32
#define NFRM  16
#define HW    192        // H*W = 8*24
#define DIM   256
#define NSLOT 21
#define NACT  20
#define ROWS_KV (BATCH*NFRM*HW)   // 98304
#define ROWS_S  (BATCH*NSLOT)     // 672
#define SLOTS_OUT_SIZE (BATCH*NACT*DIM)  // 163840
#define ATTN_EPS 1e-8f
#define LN_EPS   1e-5f
#define SCALE    0.0625f   // 256^-0.5

// ---------------- scratch (static device globals; no allocs) ----------------
__device__ float g_xn  [ROWS_KV*DIM];
__device__ float g_k   [ROWS_KV*DIM];
__device__ float g_v   [ROWS_KV*DIM];
__device__ float g_slots[ROWS_S*DIM];
__device__ float g_sln [ROWS_S*DIM];
__device__ float g_q   [ROWS_S*DIM];
__device__ float g_attn[BATCH*NSLOT*HW];
__device__ float g_upd [ROWS_S*DIM];
__device__ float g_gi  [ROWS_S*3*DIM];
__device__ float g_gh  [ROWS_S*3*DIM];
__device__ float g_h   [ROWS_S*DIM];
__device__ float g_hln [ROWS_S*DIM];
__device__ float g_f1  [ROWS_S*DIM];

// ---------------- small helpers ----------------
__device__ __forceinline__ float warpSum(float v) {
    #pragma unroll
    for (int o = 16; o; o >>= 1) v += __shfl_xor_sync(0xffffffffu, v, o);
    return v;
}

// ---------------- slots0 = mu + sigma*noise ----------------
__global__ void slots0_kernel(const float* __restrict__ noise,
                              const float* __restrict__ mu,
                              const float* __restrict__ sg,
                              float* __restrict__ slots) {
    int idx = blockIdx.x * 256 + threadIdx.x;   // 672*256 elems
    int d = idx & (DIM - 1);
    slots[idx] = mu[d] + sg[d] * noise[idx];
}

// ---------------- per-row LayerNorm over D=256; one block per row ----------------
__global__ __launch_bounds__(256) void ln_kernel(const float* __restrict__ x,
                          const float* __restrict__ g,
                          const float* __restrict__ b,
                          float* __restrict__ y) {
    __shared__ float red[8];
    int row = blockIdx.x;
    int tid = threadIdx.x;
    size_t off = (size_t)row * DIM + tid;
    float v = x[off];
    float s = warpSum(v);
    if ((tid & 31) == 0) red[tid >> 5] = s;
    __syncthreads();
    float mean = (red[0]+red[1]+red[2]+red[3]+red[4]+red[5]+red[6]+red[7]) * (1.f/DIM);
    float d = v - mean;
    __syncthreads();
    float s2 = warpSum(d * d);
    if ((tid & 31) == 0) red[tid >> 5] = s2;
    __syncthreads();
    float var = (red[0]+red[1]+red[2]+red[3]+red[4]+red[5]+red[6]+red[7]) * (1.f/DIM);
    y[off] = d * rsqrtf(var + LN_EPS) * g[tid] + b[tid];
}

// ---------------- tiled SGEMM:  C[M,N] = A[M,K] @ W[N,K]^T (+bias, +relu, +residual) ----------
#define BM 64
#define BN 64
#define BK 16
__global__ __launch_bounds__(256) void gemm_kernel(const float* __restrict__ A,
                            const float* __restrict__ W,
                            const float* __restrict__ bias,
                            const float* __restrict__ residual,
                            float* __restrict__ C,
                            int M, int N, int K, int relu) {
    __shared__ float As[BM][BK + 1];
    __shared__ float Bs[BN][BK + 1];
    int tid = threadIdx.x;
    int tx = tid & 15, ty = tid >> 4;
    int rowBase = blockIdx.y * BM;
    int colBase = blockIdx.x * BN;
    int lr = tid >> 2;          // 0..63
    int lk = (tid & 3) << 2;    // 0,4,8,12
    float acc[4][4] = {};
    for (int k0 = 0; k0 < K; k0 += BK) {
        int ar = rowBase + lr;
        float4 av = make_float4(0.f, 0.f, 0.f, 0.f);
        if (ar < M) av = *reinterpret_cast<const float4*>(A + (size_t)ar * K + k0 + lk);
        As[lr][lk+0] = av.x; As[lr][lk+1] = av.y; As[lr][lk+2] = av.z; As[lr][lk+3] = av.w;
        int br = colBase + lr;   // N is multiple of 64 -> always valid
        float4 bv = *reinterpret_cast<const float4*>(W + (size_t)br * K + k0 + lk);
        Bs[lr][lk+0] = bv.x; Bs[lr][lk+1] = bv.y; Bs[lr][lk+2] = bv.z; Bs[lr][lk+3] = bv.w;
        __syncthreads();
        #pragma unroll
        for (int kk = 0; kk < BK; kk++) {
            float a[4], b[4];
            #pragma unroll
            for (int i = 0; i < 4; i++) a[i] = As[ty*4 + i][kk];
            #pragma unroll
            for (int j = 0; j < 4; j++) b[j] = Bs[tx*4 + j][kk];
            #pragma unroll
            for (int i = 0; i < 4; i++)
                #pragma unroll
                for (int j = 0; j < 4; j++)
                    acc[i][j] = fmaf(a[i], b[j], acc[i][j]);
        }
        __syncthreads();
    }
    #pragma unroll
    for (int i = 0; i < 4; i++) {
        int r = rowBase + ty*4 + i;
        if (r >= M) continue;
        #pragma unroll
        for (int j = 0; j < 4; j++) {
            int c = colBase + tx*4 + j;
            float v = acc[i][j] + bias[c];
            if (relu) v = fmaxf(v, 0.f);
            if (residual) v += residual[(size_t)r * N + c];
            C[(size_t)r * N + c] = v;
        }
    }
}

// ---------------- fused GRU double-GEMM: z=0 -> gi = upd@W_ih^T+b_ih; z=1 -> gh = slots@W_hh^T+b_hh
__global__ __launch_bounds__(256) void gru_gemm_kernel(const float* __restrict__ upd,
                            const float* __restrict__ slots,
                            const float* __restrict__ W_ih,
                            const float* __restrict__ W_hh,
                            const float* __restrict__ b_ih,
                            const float* __restrict__ b_hh,
                            float* __restrict__ gi,
                            float* __restrict__ gh) {
    const int M = ROWS_S, N = 3 * DIM, K = DIM;
    const float* A    = blockIdx.z ? slots : upd;
    const float* W    = blockIdx.z ? W_hh  : W_ih;
    const float* bias = blockIdx.z ? b_hh  : b_ih;
    float*       C    = blockIdx.z ? gh    : gi;

    __shared__ float As[BM][BK + 1];
    __shared__ float Bs[BN][BK + 1];
    int tid = threadIdx.x;
    int tx = tid & 15, ty = tid >> 4;
    int rowBase = blockIdx.y * BM;
    int colBase = blockIdx.x * BN;
    int lr = tid >> 2;
    int lk = (tid & 3) << 2;
    float acc[4][4] = {};
    for (int k0 = 0; k0 < K; k0 += BK) {
        int ar = rowBase + lr;
        float4 av = make_float4(0.f, 0.f, 0.f, 0.f);
        if (ar < M) av = *reinterpret_cast<const float4*>(A + (size_t)ar * K + k0 + lk);
        As[lr][lk+0] = av.x; As[lr][lk+1] = av.y; As[lr][lk+2] = av.z; As[lr][lk+3] = av.w;
        int br = colBase + lr;
        float4 bv = *reinterpret_cast<const float4*>(W + (size_t)br * K + k0 + lk);
        Bs[lr][lk+0] = bv.x; Bs[lr][lk+1] = bv.y; Bs[lr][lk+2] = bv.z; Bs[lr][lk+3] = bv.w;
        __syncthreads();
        #pragma unroll
        for (int kk = 0; kk < BK; kk++) {
            float a[4], b[4];
            #pragma unroll
            for (int i = 0; i < 4; i++) a[i] = As[ty*4 + i][kk];
            #pragma unroll
            for (int j = 0; j < 4; j++) b[j] = Bs[tx*4 + j][kk];
            #pragma unroll
            for (int i = 0; i < 4; i++)
                #pragma unroll
                for (int j = 0; j < 4; j++)
                    acc[i][j] = fmaf(a[i], b[j], acc[i][j]);
        }
        __syncthreads();
    }
    #pragma unroll
    for (int i = 0; i < 4; i++) {
        int r = rowBase + ty*4 + i;
        if (r >= M) continue;
        #pragma unroll
        for (int j = 0; j < 4; j++) {
            int c = colBase + tx*4 + j;
            C[(size_t)r * N + c] = acc[i][j] + bias[c];
        }
    }
}

// ---------------- attention stage 1: dots + softmax over slot axis ----------------
#define JT 16
__global__ __launch_bounds__(256) void attn1_kernel(const float* __restrict__ q,
                             const float* __restrict__ kbuf,
                             float* __restrict__ attnO,
                             float* __restrict__ out_attn,
                             int f, int last) {
    __shared__ float q_s[NSLOT * 257];
    __shared__ float k_s[JT * 257];
    __shared__ float dots[NSLOT * JT];
    int bx = blockIdx.x;
    int b = bx / (HW / JT);
    int j0 = (bx % (HW / JT)) * JT;
    int tid = threadIdx.x;
    for (int idx = tid; idx < NSLOT * DIM; idx += 256) {
        int i = idx >> 8, d = idx & 255;
        q_s[i * 257 + d] = q[(size_t)(b * NSLOT + i) * DIM + d];
    }
    const float* kf = kbuf + ((size_t)(b * NFRM + f) * HW + j0) * DIM;
    for (int idx = tid; idx < JT * DIM; idx += 256) {
        int j = idx >> 8, d = idx & 255;
        k_s[j * 257 + d] = kf[(size_t)j * DIM + d];
    }
    __syncthreads();
    for (int p = tid; p < NSLOT * JT; p += 256) {
        int i = p / JT, j = p % JT;
        const float* qa = &q_s[i * 257];
        const float* ka = &k_s[j * 257];
        float s = 0.f;
        #pragma unroll 8
        for (int d = 0; d < DIM; d++) s = fmaf(qa[d], ka[d], s);
        dots[p] = s * SCALE;
    }
    __syncthreads();
    if (tid < JT) {
        int j = tid;
        float m = -1e30f;
        #pragma unroll
        for (int i = 0; i < NSLOT; i++) m = fmaxf(m, dots[i * JT + j]);
        float e[NSLOT];
        float sum = 0.f;
        #pragma unroll
        for (int i = 0; i < NSLOT; i++) { e[i] = expf(dots[i * JT + j] - m); sum += e[i]; }
        float inv = 1.f / sum;
        #pragma unroll
        for (int i = 0; i < NSLOT; i++) {
            float a = e[i] * inv + ATTN_EPS;
            attnO[(size_t)(b * NSLOT + i) * HW + j0 + j] = a;
            if (last)
                out_attn[((size_t)(b * NFRM + f) * NSLOT + i) * HW + j0 + j] = a;
        }
    }
}

// ---------------- attention stage 2: row-normalize + updates = attn @ v ----------------
__global__ __launch_bounds__(256) void attn2_kernel(const float* __restrict__ attnO,
                             const float* __restrict__ vbuf,
                             float* __restrict__ upd, int f) {
    __shared__ float a_s[NSLOT * 193];
    __shared__ float inv_s[NSLOT];
    __shared__ float v_s[32 * 64];
    int b = blockIdx.x >> 2;
    int d0 = (blockIdx.x & 3) * 64;
    int tid = threadIdx.x;
    for (int idx = tid; idx < NSLOT * HW; idx += 256) {
        int i = idx / HW, j = idx % HW;
        a_s[i * 193 + j] = attnO[(size_t)(b * NSLOT + i) * HW + j];
    }
    __syncthreads();
    if (tid < NSLOT) {
        float s = 0.f;
        for (int j = 0; j < HW; j++) s += a_s[tid * 193 + j];
        inv_s[tid] = 1.f / s;
    }
    __syncthreads();
    float acc[6] = {0.f, 0.f, 0.f, 0.f, 0.f, 0.f};
    const float* vf = vbuf + (size_t)(b * NFRM + f) * HW * DIM;
    for (int jt = 0; jt < 6; jt++) {
        for (int idx = tid; idx < 2048; idx += 256) {
            int jj = idx >> 6, dd = idx & 63;
            v_s[idx] = vf[(size_t)(jt * 32 + jj) * DIM + d0 + dd];
        }
        __syncthreads();
        #pragma unroll
        for (int r = 0; r < 6; r++) {
            int p = tid + r * 256;
            if (p < NSLOT * 64) {
                int i = p >> 6, dd = p & 63;
                float s = 0.f;
                #pragma unroll
                for (int jj = 0; jj < 32; jj++)
                    s = fmaf(a_s[i * 193 + jt * 32 + jj], v_s[jj * 64 + dd], s);
                acc[r] += s;
            }
        }
        __syncthreads();
    }
    #pragma unroll
    for (int r = 0; r < 6; r++) {
        int p = tid + r * 256;
        if (p < NSLOT * 64) {
            int i = p >> 6, dd = p & 63;
            upd[(size_t)(b * NSLOT + i) * DIM + d0 + dd] = acc[r] * inv_s[i];
        }
    }
}

// ---------------- fused GRU gate + LayerNorm(h) ----------------
// one block per row (256 threads = D); writes h and LN(h)
__global__ __launch_bounds__(256) void gate_ln_kernel(const float* __restrict__ gi,
                               const float* __restrict__ gh,
                               const float* __restrict__ hprev,
                               const float* __restrict__ g,
                               const float* __restrict__ be,
                               float* __restrict__ hout,
                               float* __restrict__ hln) {
    __shared__ float red[8];
    int row = blockIdx.x, d = threadIdx.x;
    size_t o3 = (size_t)row * 3 * DIM + d;
    float ir = gi[o3], iz = gi[o3 + DIM], inn = gi[o3 + 2 * DIM];
    float hr = gh[o3], hz = gh[o3 + DIM], hn  = gh[o3 + 2 * DIM];
    float hp = hprev[(size_t)row * DIM + d];
    float r = 1.f / (1.f + expf(-(ir + hr)));
    float z = 1.f / (1.f + expf(-(iz + hz)));
    float n = tanhf(inn + r * hn);
    float h = (1.f - z) * n + z * hp;
    hout[(size_t)row * DIM + d] = h;
    // LayerNorm(h)
    float s = warpSum(h);
    if ((d & 31) == 0) red[d >> 5] = s;
    __syncthreads();
    float mean = (red[0]+red[1]+red[2]+red[3]+red[4]+red[5]+red[6]+red[7]) * (1.f/DIM);
    float dv = h - mean;
    __syncthreads();
    float s2 = warpSum(dv * dv);
    if ((d & 31) == 0) red[d >> 5] = s2;
    __syncthreads();
    float var = (red[0]+red[1]+red[2]+red[3]+red[4]+red[5]+red[6]+red[7]) * (1.f/DIM);
    hln[(size_t)row * DIM + d] = dv * rsqrtf(var + LN_EPS) * g[d] + be[d];
}

// ---------------- final slots copy (first 20 of 21 slots) ----------------
__global__ void copy_slots_kernel(const float* __restrict__ slots, float* __restrict__ out) {
    int idx = blockIdx.x * 256 + threadIdx.x;   // 163840
    int d = idx & 255;
    int s = (idx >> 8) % NACT;
    int b = idx / (NACT * DIM);
    out[idx] = slots[((size_t)(b * NSLOT + s) << 8) + d];
}

// ---------------- launch ----------------
extern "C" void kernel_launch(void* const* d_in, const int* in_sizes, int n_in,
                              void* d_out, int out_size) {
    const float* inputs = (const float*)d_in[0];
    const float* noise  = (const float*)d_in[1];
    const float* mu     = (const float*)d_in[2];
    const float* sigma  = (const float*)d_in[3];
    const float* Wq = (const float*)d_in[4];  const float* bq = (const float*)d_in[5];
    const float* Wk = (const float*)d_in[6];  const float* bk = (const float*)d_in[7];
    const float* Wv = (const float*)d_in[8];  const float* bv = (const float*)d_in[9];
    const float* W1 = (const float*)d_in[10]; const float* b1 = (const float*)d_in[11];
    const float* W2 = (const float*)d_in[12]; const float* b2 = (const float*)d_in[13];
    const float* W_ih = (const float*)d_in[14]; const float* b_ih = (const float*)d_in[15];
    const float* W_hh = (const float*)d_in[16]; const float* b_hh = (const float*)d_in[17];
    const float* g_in_p = (const float*)d_in[18]; const float* be_in = (const float*)d_in[19];
    const float* g_sl_p = (const float*)d_in[20]; const float* be_sl = (const float*)d_in[21];
    const float* g_ff_p = (const float*)d_in[22]; const float* be_ff = (const float*)d_in[23];
    float* out = (float*)d_out;

    float *xn, *kb, *vb, *slots, *sln, *qb, *attnO, *upd, *gi, *gh, *hb, *hln, *f1;
    cudaGetSymbolAddress((void**)&xn,    g_xn);
    cudaGetSymbolAddress((void**)&kb,    g_k);
    cudaGetSymbolAddress((void**)&vb,    g_v);
    cudaGetSymbolAddress((void**)&slots, g_slots);
    cudaGetSymbolAddress((void**)&sln,   g_sln);
    cudaGetSymbolAddress((void**)&qb,    g_q);
    cudaGetSymbolAddress((void**)&attnO, g_attn);
    cudaGetSymbolAddress((void**)&upd,   g_upd);
    cudaGetSymbolAddress((void**)&gi,    g_gi);
    cudaGetSymbolAddress((void**)&gh,    g_gh);
    cudaGetSymbolAddress((void**)&hb,    g_h);
    cudaGetSymbolAddress((void**)&hln,   g_hln);
    cudaGetSymbolAddress((void**)&f1,    g_f1);

    // slots0 = mu + sigma * noise
    slots0_kernel<<<ROWS_S, 256>>>(noise, mu, sigma, slots);

    // Hoisted: LN(inputs) then K/V projections for ALL frames (parallel)
    ln_kernel<<<ROWS_KV, 256>>>(inputs, g_in_p, be_in, xn);
    dim3 gkv(DIM / BN, (ROWS_KV + BM - 1) / BM);
    gemm_kernel<<<gkv, 256>>>(xn, Wk, bk, nullptr, kb, ROWS_KV, DIM, DIM, 0);
    gemm_kernel<<<gkv, 256>>>(xn, Wv, bv, nullptr, vb, ROWS_KV, DIM, DIM, 0);

    dim3 gS  (DIM / BN,     (ROWS_S + BM - 1) / BM);     // (4, 11)
    dim3 gS3 (3 * DIM / BN, (ROWS_S + BM - 1) / BM, 2);  // (12, 11, 2)
    float* attn_out = out + SLOTS_OUT_SIZE;

    for (int f = 0; f < NFRM; f++) {
        for (int it = 0; it < 3; it++) {
            ln_kernel<<<ROWS_S, 256>>>(slots, g_sl_p, be_sl, sln);
            gemm_kernel<<<gS, 256>>>(sln, Wq, bq, nullptr, qb, ROWS_S, DIM, DIM, 0);
            attn1_kernel<<<BATCH * (HW / JT), 256>>>(qb, kb, attnO, attn_out, f, it == 2);
            attn2_kernel<<<BATCH * 4, 256>>>(attnO, vb, upd, f);
            gru_gemm_kernel<<<gS3, 256>>>(upd, slots, W_ih, W_hh, b_ih, b_hh, gi, gh);
            gate_ln_kernel<<<ROWS_S, 256>>>(gi, gh, slots, g_ff_p, be_ff, hb, hln);
            gemm_kernel<<<gS, 256>>>(hln, W1, b1, nullptr, f1, ROWS_S, DIM, DIM, 1);
            gemm_kernel<<<gS, 256>>>(f1, W2, b2, hb, slots, ROWS_S, DIM, DIM, 0);
        }
    }

    copy_slots_kernel<<<SLOTS_OUT_SIZE / 256, 256>>>(slots, out);
}

// round 4
// speedup vs baseline: 1.1505x; 1.1505x over previous
#include <cuda_runtime.h>
#include <cuda_bf16.h>
#include <math.h>

// ---------------- problem constants ----------------
#define BATCH 32
#define NFRM  16
#define HW    192        // H*W = 8*24
#define DIM   256
#define NSLOT 21
#define NACT  20
#define ROWS_KV (BATCH*NFRM*HW)   // 98304
#define ROWS_S  (BATCH*NSLOT)     // 672
#define SLOTS_OUT_SIZE (BATCH*NACT*DIM)  // 163840
#define ATTN_EPS 1e-8f
#define LN_EPS   1e-5f
#define SCALE    0.0625f   // 256^-0.5

// ---------------- scratch (static device globals; no allocs) ----------------
__device__ float g_xn  [ROWS_KV*DIM];
__device__ float g_k   [ROWS_KV*DIM];
__device__ float g_v   [ROWS_KV*DIM];
__device__ float g_slots[ROWS_S*DIM];
__device__ float g_q   [ROWS_S*DIM];
__device__ float g_attn[BATCH*NSLOT*HW];
__device__ float g_upd [ROWS_S*DIM];
__device__ float g_gi  [ROWS_S*3*DIM];
__device__ float g_gh  [ROWS_S*3*DIM];
__device__ float g_h   [ROWS_S*DIM];
__device__ float g_f1  [ROWS_S*DIM];

// ---------------- smem layout (floats) for persistent kernel ----------------
#define LDA     260            // row stride for 21x256 activation buffers (mult of 4)
#define SZ_ACT  (NSLOT*LDA)    // 5460
#define OFF_SLOTS 0
#define OFF_SLN   (OFF_SLOTS + SZ_ACT)
#define OFF_Q     (OFF_SLN   + SZ_ACT)
#define OFF_UPD   (OFF_Q     + SZ_ACT)
#define OFF_H     (OFF_UPD   + SZ_ACT)
#define OFF_HLN   (OFF_H     + SZ_ACT)
#define OFF_F1    (OFF_HLN   + SZ_ACT)
#define LDATTN    196
#define OFF_ATTN  (OFF_F1    + SZ_ACT)          // 21*196 = 4116
#define LDDOT     52
#define OFF_DOTS  (OFF_ATTN  + NSLOT*LDATTN)    // 21*52 = 1092
#define OFF_INV   (OFF_DOTS  + NSLOT*LDDOT)     // 32
#define OFF_LNP   (OFF_INV   + 32)              // 4*256 LN params
#define OFF_W     (OFF_LNP   + 1024)            // 64*36 = 2304
#define OFF_V     (OFF_W     + 64*36)           // 32*68 = 2176
#define SMEM_FLOATS (OFF_V + 32*68)             // 48964
#define SMEM_BYTES  (SMEM_FLOATS*4)             // 195856

// ---------------- small helpers ----------------
__device__ __forceinline__ float warpSum(float v) {
    #pragma unroll
    for (int o = 16; o; o >>= 1) v += __shfl_xor_sync(0xffffffffu, v, o);
    return v;
}

__device__ __forceinline__ void cluster_sync_all() {
    asm volatile("barrier.cluster.arrive.aligned;\n\tbarrier.cluster.wait.aligned;" ::: "memory");
}

// ---------------- slots0 = mu + sigma*noise ----------------
__global__ void slots0_kernel(const float* __restrict__ noise,
                              const float* __restrict__ mu,
                              const float* __restrict__ sg,
                              float* __restrict__ slots) {
    int idx = blockIdx.x * 256 + threadIdx.x;   // 672*256 elems
    int d = idx & (DIM - 1);
    slots[idx] = mu[d] + sg[d] * noise[idx];
}

// ---------------- per-row LayerNorm over D=256 (inputs path) ----------------
__global__ __launch_bounds__(256) void ln_kernel(const float* __restrict__ x,
                          const float* __restrict__ g,
                          const float* __restrict__ b,
                          float* __restrict__ y) {
    __shared__ float red[8];
    int row = blockIdx.x;
    int tid = threadIdx.x;
    size_t off = (size_t)row * DIM + tid;
    float v = x[off];
    float s = warpSum(v);
    if ((tid & 31) == 0) red[tid >> 5] = s;
    __syncthreads();
    float mean = (red[0]+red[1]+red[2]+red[3]+red[4]+red[5]+red[6]+red[7]) * (1.f/DIM);
    float d = v - mean;
    __syncthreads();
    float s2 = warpSum(d * d);
    if ((tid & 31) == 0) red[tid >> 5] = s2;
    __syncthreads();
    float var = (red[0]+red[1]+red[2]+red[3]+red[4]+red[5]+red[6]+red[7]) * (1.f/DIM);
    y[off] = d * rsqrtf(var + LN_EPS) * g[tid] + b[tid];
}

// ---------------- tiled SGEMM for the big KV projections ----------
#define BM 64
#define BN 64
#define BK 16
__global__ __launch_bounds__(256) void gemm_kernel(const float* __restrict__ A,
                            const float* __restrict__ W,
                            const float* __restrict__ bias,
                            float* __restrict__ C,
                            int M, int N, int K) {
    __shared__ float As[BM][BK + 1];
    __shared__ float Bs[BN][BK + 1];
    int tid = threadIdx.x;
    int tx = tid & 15, ty = tid >> 4;
    int rowBase = blockIdx.y * BM;
    int colBase = blockIdx.x * BN;
    int lr = tid >> 2;
    int lk = (tid & 3) << 2;
    float acc[4][4] = {};
    for (int k0 = 0; k0 < K; k0 += BK) {
        int ar = rowBase + lr;
        float4 av = make_float4(0.f, 0.f, 0.f, 0.f);
        if (ar < M) av = *reinterpret_cast<const float4*>(A + (size_t)ar * K + k0 + lk);
        As[lr][lk+0] = av.x; As[lr][lk+1] = av.y; As[lr][lk+2] = av.z; As[lr][lk+3] = av.w;
        int br = colBase + lr;
        float4 bv = *reinterpret_cast<const float4*>(W + (size_t)br * K + k0 + lk);
        Bs[lr][lk+0] = bv.x; Bs[lr][lk+1] = bv.y; Bs[lr][lk+2] = bv.z; Bs[lr][lk+3] = bv.w;
        __syncthreads();
        #pragma unroll
        for (int kk = 0; kk < BK; kk++) {
            float a[4], b[4];
            #pragma unroll
            for (int i = 0; i < 4; i++) a[i] = As[ty*4 + i][kk];
            #pragma unroll
            for (int j = 0; j < 4; j++) b[j] = Bs[tx*4 + j][kk];
            #pragma unroll
            for (int i = 0; i < 4; i++)
                #pragma unroll
                for (int j = 0; j < 4; j++)
                    acc[i][j] = fmaf(a[i], b[j], acc[i][j]);
        }
        __syncthreads();
    }
    #pragma unroll
    for (int i = 0; i < 4; i++) {
        int r = rowBase + ty*4 + i;
        if (r >= M) continue;
        #pragma unroll
        for (int j = 0; j < 4; j++) {
            int c = colBase + tx*4 + j;
            C[(size_t)r * N + c] = acc[i][j] + bias[c];
        }
    }
}

// ============================================================================
// Persistent per-batch cluster kernel: entire 16-frame x 3-iteration loop.
// grid = 128 CTAs, cluster (4,1,1): cluster index = batch element b,
// rank r = blockIdx.x & 3 computes a column slice of every GEMM.
// Inter-rank exchange via global memory + barrier.cluster (which flushes L1D).
// ============================================================================

// one <=64-column GEMM tile: acc[i][c] = sum_k s_a[i][k] * W[c][k]
// A: smem [21][LDA]; W: global (pre-offset), rows x 256, row-major.
// epilogue: *scale, +bias, relu, +smem residual, store to global and/or smem.
__device__ __forceinline__ void small_gemm(
    const float* __restrict__ s_a,
    float* __restrict__ s_w,
    const float* __restrict__ W,
    const float* __restrict__ bias,
    int ncols, float scale, int relu,
    const float* __restrict__ s_res, int res_off,
    float* __restrict__ g_out, int g_ld,
    float* __restrict__ s_out, int s_ld)
{
    int tid = threadIdx.x;
    int c   = tid & 63;
    int grp = tid >> 6;
    int wr  = tid >> 2;          // 0..63
    int wk  = (tid & 3) * 8;     // 0,8,16,24
    float acc[6] = {0.f,0.f,0.f,0.f,0.f,0.f};
    for (int k0 = 0; k0 < 256; k0 += 32) {
        float4 w0 = make_float4(0.f,0.f,0.f,0.f), w1 = w0;
        if (wr < ncols) {
            const float* wp = W + (size_t)wr * 256 + k0 + wk;
            w0 = *reinterpret_cast<const float4*>(wp);
            w1 = *reinterpret_cast<const float4*>(wp + 4);
        }
        __syncthreads();   // previous consumers of s_w done
        *reinterpret_cast<float4*>(&s_w[wr*36 + wk])     = w0;
        *reinterpret_cast<float4*>(&s_w[wr*36 + wk + 4]) = w1;
        __syncthreads();
        #pragma unroll
        for (int kk = 0; kk < 32; kk += 4) {
            float4 w4 = *reinterpret_cast<float4*>(&s_w[c*36 + kk]);
            #pragma unroll
            for (int u = 0; u < 6; u++) {
                int row = grp + 4*u;
                if (row < NSLOT) {
                    float4 a4 = *reinterpret_cast<const float4*>(&s_a[row*LDA + k0 + kk]);
                    acc[u] = fmaf(a4.x, w4.x, acc[u]);
                    acc[u] = fmaf(a4.y, w4.y, acc[u]);
                    acc[u] = fmaf(a4.z, w4.z, acc[u]);
                    acc[u] = fmaf(a4.w, w4.w, acc[u]);
                }
            }
        }
    }
    if (c < ncols) {
        float bv = bias ? bias[c] : 0.f;
        #pragma unroll
        for (int u = 0; u < 6; u++) {
            int row = grp + 4*u;
            if (row < NSLOT) {
                float rv = acc[u] * scale + bv;
                if (relu) rv = fmaxf(rv, 0.f);
                if (s_res) rv += s_res[row*LDA + res_off + c];
                if (g_out) g_out[(size_t)row * g_ld + c] = rv;
                if (s_out) s_out[row * s_ld + c] = rv;
            }
        }
    }
}

// updates slice: upd[i][d0+c] = inv[i] * sum_j attn[i][j] * v[j][d0+c]
__device__ __forceinline__ void attn_av(
    const float* __restrict__ s_attn,
    const float* __restrict__ s_inv,
    float* __restrict__ s_v,
    const float* __restrict__ vbase,   // frame base + d0
    float* __restrict__ g_out)         // upd base + d0
{
    int tid = threadIdx.x;
    int c   = tid & 63;
    int grp = tid >> 6;
    int vr  = tid >> 3;          // 0..31
    int vc  = (tid & 7) * 8;     // 0..56
    float acc[6] = {0.f,0.f,0.f,0.f,0.f,0.f};
    for (int j0 = 0; j0 < HW; j0 += 32) {
        const float* vp = vbase + (size_t)(j0 + vr) * 256 + vc;
        float4 v0 = *reinterpret_cast<const float4*>(vp);
        float4 v1 = *reinterpret_cast<const float4*>(vp + 4);
        __syncthreads();
        *reinterpret_cast<float4*>(&s_v[vr*68 + vc])     = v0;
        *reinterpret_cast<float4*>(&s_v[vr*68 + vc + 4]) = v1;
        __syncthreads();
        #pragma unroll
        for (int jj = 0; jj < 32; jj += 4) {
            float w0 = s_v[(jj+0)*68 + c];
            float w1 = s_v[(jj+1)*68 + c];
            float w2 = s_v[(jj+2)*68 + c];
            float w3 = s_v[(jj+3)*68 + c];
            #pragma unroll
            for (int u = 0; u < 6; u++) {
                int row = grp + 4*u;
                if (row < NSLOT) {
                    float4 a4 = *reinterpret_cast<const float4*>(&s_attn[row*LDATTN + j0 + jj]);
                    acc[u] = fmaf(a4.x, w0, acc[u]);
                    acc[u] = fmaf(a4.y, w1, acc[u]);
                    acc[u] = fmaf(a4.z, w2, acc[u]);
                    acc[u] = fmaf(a4.w, w3, acc[u]);
                }
            }
        }
    }
    #pragma unroll
    for (int u = 0; u < 6; u++) {
        int row = grp + 4*u;
        if (row < NSLOT) g_out[(size_t)row * 256 + c] = acc[u] * s_inv[row];
    }
}

// per-row LN of smem 21x256 (warp per row), params from smem
__device__ __forceinline__ void ln_rows(const float* __restrict__ s_src,
                                        float* __restrict__ s_dst,
                                        const float* __restrict__ gg,
                                        const float* __restrict__ bb)
{
    int tid = threadIdx.x;
    int w = tid >> 5, lane = tid & 31;
    for (int row = w; row < NSLOT; row += 8) {
        const float* src = s_src + row*LDA;
        float v[8]; float s = 0.f;
        #pragma unroll
        for (int m = 0; m < 8; m++) { v[m] = src[lane + 32*m]; s += v[m]; }
        s = warpSum(s);
        float mean = s * (1.f/256.f);
        float s2 = 0.f;
        #pragma unroll
        for (int m = 0; m < 8; m++) { float d = v[m]-mean; s2 += d*d; }
        s2 = warpSum(s2);
        float inv = rsqrtf(s2 * (1.f/256.f) + LN_EPS);
        float* dst = s_dst + row*LDA;
        #pragma unroll
        for (int m = 0; m < 8; m++) {
            int d = lane + 32*m;
            dst[d] = (v[m]-mean) * inv * gg[d] + bb[d];
        }
    }
}

// load 21x256 global (ld 256) -> smem (ld LDA)
__device__ __forceinline__ void load_act(float* __restrict__ s_dst,
                                         const float* __restrict__ g_src)
{
    int tid = threadIdx.x;
    for (int i = tid; i < NSLOT*64; i += 256) {
        int row = i >> 6, c4 = i & 63;
        *reinterpret_cast<float4*>(&s_dst[row*LDA + c4*4]) =
            *reinterpret_cast<const float4*>(&g_src[(size_t)row*256 + c4*4]);
    }
}

__global__ void __cluster_dims__(4,1,1) __launch_bounds__(256,1)
slot_iter_kernel(const float* __restrict__ kb, const float* __restrict__ vb,
                 float* __restrict__ slots_g, float* __restrict__ q_g,
                 float* __restrict__ attn_g, float* __restrict__ upd_g,
                 float* __restrict__ gi_g, float* __restrict__ gh_g,
                 float* __restrict__ h_g, float* __restrict__ f1_g,
                 const float* __restrict__ Wq, const float* __restrict__ bq,
                 const float* __restrict__ W1, const float* __restrict__ b1,
                 const float* __restrict__ W2, const float* __restrict__ b2,
                 const float* __restrict__ W_ih, const float* __restrict__ b_ih,
                 const float* __restrict__ W_hh, const float* __restrict__ b_hh,
                 const float* __restrict__ g_sl, const float* __restrict__ be_sl,
                 const float* __restrict__ g_ff, const float* __restrict__ be_ff,
                 float* __restrict__ out_attn)
{
    extern __shared__ float sm[];
    int tid = threadIdx.x;
    int b = blockIdx.x >> 2;
    int r = blockIdx.x & 3;

    float* s_slots = sm + OFF_SLOTS;
    float* s_sln   = sm + OFF_SLN;
    float* s_q     = sm + OFF_Q;
    float* s_upd   = sm + OFF_UPD;
    float* s_h     = sm + OFF_H;
    float* s_hln   = sm + OFF_HLN;
    float* s_f1    = sm + OFF_F1;
    float* s_attn  = sm + OFF_ATTN;
    float* s_dots  = sm + OFF_DOTS;
    float* s_inv   = sm + OFF_INV;
    float* s_lnp   = sm + OFF_LNP;
    float* s_w     = sm + OFF_W;
    float* s_v     = sm + OFF_V;

    // per-batch global slices
    float* slots_b = slots_g + (size_t)b * NSLOT * 256;
    float* q_b     = q_g     + (size_t)b * NSLOT * 256;
    float* attn_b  = attn_g  + (size_t)b * NSLOT * HW;
    float* upd_b   = upd_g   + (size_t)b * NSLOT * 256;
    float* gi_b    = gi_g    + (size_t)b * NSLOT * 768;
    float* gh_b    = gh_g    + (size_t)b * NSLOT * 768;
    float* h_b     = h_g     + (size_t)b * NSLOT * 256;
    float* f1_b    = f1_g    + (size_t)b * NSLOT * 256;

    // preload LN params + initial slots
    for (int i = tid; i < 256; i += 256) {
        s_lnp[i]       = g_sl[i];
        s_lnp[i + 256] = be_sl[i];
        s_lnp[i + 512] = g_ff[i];
        s_lnp[i + 768] = be_ff[i];
    }
    load_act(s_slots, slots_b);
    __syncthreads();

    for (int f = 0; f < NFRM; f++) {
        const float* kf = kb + (size_t)(b*NFRM + f) * HW * 256;
        const float* vf = vb + (size_t)(b*NFRM + f) * HW * 256;
        for (int it = 0; it < 3; it++) {
            // ---- A: LN(slots) -> q slice ----
            ln_rows(s_slots, s_sln, s_lnp, s_lnp + 256);
            __syncthreads();
            small_gemm(s_sln, s_w, Wq + (size_t)r*64*256, bq + r*64,
                       64, 1.f, 0, nullptr, 0, q_b + r*64, 256, nullptr, 0);
            cluster_sync_all();
            load_act(s_q, q_b);
            __syncthreads();

            // ---- B1: dots slice + softmax over slots (per j) ----
            small_gemm(s_q, s_w, kf + (size_t)r*48*256, nullptr,
                       48, SCALE, 0, nullptr, 0, nullptr, 0, s_dots, LDDOT);
            __syncthreads();
            if (tid < 48) {
                int j = tid;
                float m = -1e30f;
                #pragma unroll
                for (int i = 0; i < NSLOT; i++) m = fmaxf(m, s_dots[i*LDDOT + j]);
                float e[NSLOT]; float sum = 0.f;
                #pragma unroll
                for (int i = 0; i < NSLOT; i++) { e[i] = expf(s_dots[i*LDDOT + j] - m); sum += e[i]; }
                float inv = 1.f / sum;
                int jg = r*48 + j;
                float* oa = out_attn + ((size_t)(b*NFRM + f) * NSLOT) * HW;
                #pragma unroll
                for (int i = 0; i < NSLOT; i++) {
                    float a = e[i]*inv + ATTN_EPS;
                    attn_b[(size_t)i*HW + jg] = a;
                    if (it == 2) oa[(size_t)i*HW + jg] = a;
                }
            }
            cluster_sync_all();

            // ---- B2: row-normalize + updates slice ----
            {
                // load full attn 21x192 -> smem (ld LDATTN)
                for (int i = tid; i < NSLOT*48; i += 256) {
                    int row = i / 48, c4 = i % 48;
                    *reinterpret_cast<float4*>(&s_attn[row*LDATTN + c4*4]) =
                        *reinterpret_cast<const float4*>(&attn_b[(size_t)row*HW + c4*4]);
                }
                __syncthreads();
                int w = tid >> 5, lane = tid & 31;
                for (int row = w; row < NSLOT; row += 8) {
                    float s = 0.f;
                    for (int j = lane; j < HW; j += 32) s += s_attn[row*LDATTN + j];
                    s = warpSum(s);
                    if (lane == 0) s_inv[row] = 1.f / s;
                }
                __syncthreads();
            }
            attn_av(s_attn, s_inv, s_v, vf + r*64, upd_b + r*64);
            cluster_sync_all();
            load_act(s_upd, upd_b);
            __syncthreads();

            // ---- C: GRU gemms (gi from upd, gh from raw slots), 192 cols each ----
            #pragma unroll
            for (int t = 0; t < 3; t++) {
                int cb = r*192 + t*64;
                small_gemm(s_upd, s_w, W_ih + (size_t)cb*256, b_ih + cb,
                           64, 1.f, 0, nullptr, 0, gi_b + cb, 768, nullptr, 0);
                small_gemm(s_slots, s_w, W_hh + (size_t)cb*256, b_hh + cb,
                           64, 1.f, 0, nullptr, 0, gh_b + cb, 768, nullptr, 0);
            }
            cluster_sync_all();

            // ---- gate ----
            for (int idx = tid; idx < NSLOT*64; idx += 256) {
                int i = idx >> 6; int d = r*64 + (idx & 63);
                const float* gir = gi_b + (size_t)i*768;
                const float* ghr = gh_b + (size_t)i*768;
                float ir = gir[d], iz = gir[d+256], inn = gir[d+512];
                float hr = ghr[d], hz = ghr[d+256], hn  = ghr[d+512];
                float hp = s_slots[i*LDA + d];
                float rr = 1.f / (1.f + expf(-(ir + hr)));
                float zz = 1.f / (1.f + expf(-(iz + hz)));
                float nn = tanhf(inn + rr * hn);
                h_b[(size_t)i*256 + d] = (1.f - zz) * nn + zz * hp;
            }
            cluster_sync_all();
            load_act(s_h, h_b);
            __syncthreads();
            ln_rows(s_h, s_hln, s_lnp + 512, s_lnp + 768);
            __syncthreads();

            // ---- D: MLP ----
            small_gemm(s_hln, s_w, W1 + (size_t)r*64*256, b1 + r*64,
                       64, 1.f, 1, nullptr, 0, f1_b + r*64, 256, nullptr, 0);
            cluster_sync_all();
            load_act(s_f1, f1_b);
            __syncthreads();
            small_gemm(s_f1, s_w, W2 + (size_t)r*64*256, b2 + r*64,
                       64, 1.f, 0, s_h, r*64, slots_b + r*64, 256, nullptr, 0);
            cluster_sync_all();
            load_act(s_slots, slots_b);
            __syncthreads();
        }
    }
}

// ---------------- final slots copy (first 20 of 21 slots) ----------------
__global__ void copy_slots_kernel(const float* __restrict__ slots, float* __restrict__ out) {
    int idx = blockIdx.x * 256 + threadIdx.x;   // 163840
    int d = idx & 255;
    int s = (idx >> 8) % NACT;
    int b = idx / (NACT * DIM);
    out[idx] = slots[((size_t)(b * NSLOT + s) << 8) + d];
}

// ---------------- launch ----------------
extern "C" void kernel_launch(void* const* d_in, const int* in_sizes, int n_in,
                              void* d_out, int out_size) {
    const float* inputs = (const float*)d_in[0];
    const float* noise  = (const float*)d_in[1];
    const float* mu     = (const float*)d_in[2];
    const float* sigma  = (const float*)d_in[3];
    const float* Wq = (const float*)d_in[4];  const float* bq = (const float*)d_in[5];
    const float* Wk = (const float*)d_in[6];  const float* bk = (const float*)d_in[7];
    const float* Wv = (const float*)d_in[8];  const float* bv = (const float*)d_in[9];
    const float* W1 = (const float*)d_in[10]; const float* b1 = (const float*)d_in[11];
    const float* W2 = (const float*)d_in[12]; const float* b2 = (const float*)d_in[13];
    const float* W_ih = (const float*)d_in[14]; const float* b_ih = (const float*)d_in[15];
    const float* W_hh = (const float*)d_in[16]; const float* b_hh = (const float*)d_in[17];
    const float* g_in_p = (const float*)d_in[18]; const float* be_in = (const float*)d_in[19];
    const float* g_sl_p = (const float*)d_in[20]; const float* be_sl = (const float*)d_in[21];
    const float* g_ff_p = (const float*)d_in[22]; const float* be_ff = (const float*)d_in[23];
    float* out = (float*)d_out;

    float *xn, *kb, *vb, *slots, *qb, *attnO, *upd, *gi, *gh, *hb, *f1;
    cudaGetSymbolAddress((void**)&xn,    g_xn);
    cudaGetSymbolAddress((void**)&kb,    g_k);
    cudaGetSymbolAddress((void**)&vb,    g_v);
    cudaGetSymbolAddress((void**)&slots, g_slots);
    cudaGetSymbolAddress((void**)&qb,    g_q);
    cudaGetSymbolAddress((void**)&attnO, g_attn);
    cudaGetSymbolAddress((void**)&upd,   g_upd);
    cudaGetSymbolAddress((void**)&gi,    g_gi);
    cudaGetSymbolAddress((void**)&gh,    g_gh);
    cudaGetSymbolAddress((void**)&hb,    g_h);
    cudaGetSymbolAddress((void**)&f1,    g_f1);

    static int smem_set = 0;
    if (!smem_set) {
        cudaFuncSetAttribute(slot_iter_kernel,
                             cudaFuncAttributeMaxDynamicSharedMemorySize, SMEM_BYTES);
        smem_set = 1;
    }

    // slots0 = mu + sigma * noise
    slots0_kernel<<<ROWS_S, 256>>>(noise, mu, sigma, slots);

    // Hoisted: LN(inputs) then K/V projections for ALL frames
    ln_kernel<<<ROWS_KV, 256>>>(inputs, g_in_p, be_in, xn);
    dim3 gkv(DIM / BN, (ROWS_KV + BM - 1) / BM);
    gemm_kernel<<<gkv, 256>>>(xn, Wk, bk, kb, ROWS_KV, DIM, DIM);
    gemm_kernel<<<gkv, 256>>>(xn, Wv, bv, vb, ROWS_KV, DIM, DIM);

    // Entire 16x3 sequential loop in one persistent cluster kernel
    float* attn_out = out + SLOTS_OUT_SIZE;
    slot_iter_kernel<<<BATCH * 4, 256, SMEM_BYTES>>>(
        kb, vb, slots, qb, attnO, upd, gi, gh, hb, f1,
        Wq, bq, W1, b1, W2, b2, W_ih, b_ih, W_hh, b_hh,
        g_sl_p, be_sl, g_ff_p, be_ff, attn_out);

    copy_slots_kernel<<<SLOTS_OUT_SIZE / 256, 256>>>(slots, out);
}